// round 4
// baseline (speedup 1.0000x reference)
#include <cuda_runtime.h>
#include <cstdint>

typedef unsigned long long ull;
typedef unsigned int uint;

// ---------------- packed fp32x2 helpers (PTX-only FFMA2 path) ----------------
__device__ __forceinline__ ull pack2(float lo, float hi) {
    ull r; asm("mov.b64 %0, {%1, %2};" : "=l"(r) : "f"(lo), "f"(hi)); return r;
}
__device__ __forceinline__ void fma2(ull& acc, ull a, ull b) {
    asm("fma.rn.f32x2 %0, %1, %2, %0;" : "+l"(acc) : "l"(a), "l"(b));
}
__device__ __forceinline__ float2 unpack2(ull v) {
    float2 r; asm("mov.b64 {%0, %1}, %2;" : "=f"(r.x), "=f"(r.y) : "l"(v)); return r;
}
__device__ __forceinline__ float sigmoidf(float x) {
    return __fdividef(1.0f, 1.0f + __expf(-x));
}

// xg scratch: [l][g][n][a][b]  (3*128*64*64*64 floats = 384 MB, device .bss)
__device__ float g_xg[(size_t)3 * 128 * 64 * 64 * 64];

// ============================================================================
// Phase 1 (unchanged from round 2 — validated):
// xg[l,g,n,a,b] = sum_{i,j} Ww1[g,a,i] * x[l,n,i,j] * Ww2[g,b,j]
// ============================================================================
#define SX 68

__device__ __forceinline__ void mm_tile44(const float* AT, const float* B,
                                          int m0, int n0, ull acc[4][2]) {
#pragma unroll 8
    for (int k = 0; k < 64; ++k) {
        float4 av = *(const float4*)(AT + k * SX + m0);
        float4 bv = *(const float4*)(B  + k * SX + n0);
        ull b01 = pack2(bv.x, bv.y), b23 = pack2(bv.z, bv.w);
        ull a;
        a = pack2(av.x, av.x); fma2(acc[0][0], a, b01); fma2(acc[0][1], a, b23);
        a = pack2(av.y, av.y); fma2(acc[1][0], a, b01); fma2(acc[1][1], a, b23);
        a = pack2(av.z, av.z); fma2(acc[2][0], a, b01); fma2(acc[2][1], a, b23);
        a = pack2(av.w, av.w); fma2(acc[3][0], a, b01); fma2(acc[3][1], a, b23);
    }
}
__device__ __forceinline__ void zero_acc44(ull acc[4][2]) {
#pragma unroll
    for (int r = 0; r < 4; ++r) { acc[r][0] = pack2(0.f,0.f); acc[r][1] = pack2(0.f,0.f); }
}

__global__ void __launch_bounds__(256, 2)
xg_kernel(const float* __restrict__ inputs,
          const float* __restrict__ Ww1,
          const float* __restrict__ Ww2) {
    extern __shared__ float sm[];
    float* xs   = sm;
    float* w1T  = sm + 64 * SX;
    float* w2T  = sm + 2 * 64 * SX;
    float* tmpT = sm + 3 * 64 * SX;

    const int l = blockIdx.x, n = blockIdx.y;
    const int tid = threadIdx.x;
    const int ty = tid >> 4, tx = tid & 15;
    const int m0 = ty * 4, n0 = tx * 4;

    const float* xsrc = inputs + ((size_t)n * 128 + l) * 4096;
    for (int e = tid; e < 1024; e += 256) {
        int i = e >> 4, j4 = (e & 15) * 4;
        *(float4*)(xs + i * SX + j4) = *(const float4*)(xsrc + i * 64 + j4);
    }

    for (int g = 0; g < 3; ++g) {
        __syncthreads();
        const float* w1 = Ww1 + g * 4096;
        const float* w2 = Ww2 + g * 4096;
        for (int e = tid; e < 4096; e += 256) {
            int r = e >> 6, cc = e & 63;
            w1T[cc * SX + r] = w1[e];
            w2T[cc * SX + r] = w2[e];
        }
        __syncthreads();

        ull acc[4][2];
        zero_acc44(acc);
        mm_tile44(xs, w1T, m0, n0, acc);          // tmpT[j][a]
#pragma unroll
        for (int r = 0; r < 4; ++r) {
            float2 lo = unpack2(acc[r][0]), hi = unpack2(acc[r][1]);
            *(float4*)(tmpT + (m0 + r) * SX + n0) = make_float4(lo.x, lo.y, hi.x, hi.y);
        }
        __syncthreads();

        zero_acc44(acc);
        mm_tile44(tmpT, w2T, m0, n0, acc);        // xg[a][b]
        float* dst = g_xg + ((size_t)(l * 3 + g) * 64 + n) * 4096;
#pragma unroll
        for (int r = 0; r < 4; ++r) {
            float2 lo = unpack2(acc[r][0]), hi = unpack2(acc[r][1]);
            *(float4*)(dst + (m0 + r) * 64 + n0) = make_float4(lo.x, lo.y, hi.x, hi.y);
        }
    }
}

// ============================================================================
// Phase 2: recurrence, cluster-2 + gate-parallel.
//   128 CTAs (= 64 n x 2 ranks), 768 threads = 3 gate-groups of 256.
//   CTA rank owns output rows a in [32*rank, 32*rank+32).
//   Stage1: tmpT[g][j][a_l] = sum_i h[i][j] * Wu1[g][a][i]     (M=64 j, N=32 a_l)
//   Stage2: hg[g][a_l][b]   = sum_j tmpT[g][j][a_l] * Wu2[g][b][j] (M=32, N=64)
//   Gate exchange via smem buf; h exchange via DSMEM; ping-pong h buffers ->
//   ONE cluster barrier per step.
// ============================================================================
#define W1X 32   // w1T row stride: [i][a_l]
#define W2X 64   // w2T row stride: [j][b]
#define TPX 36   // tmpT row stride: [j][a_l] (pad for store conflicts)
#define HX  64   // h row stride: [i][j]
#define BFX 68   // gate buf row stride: [a_l][b]

// 2x4 register tile: C[m0..m0+1][n0..n0+3] += sum_k AT[k][m] * B[k][n]
template <int SA, int SB>
__device__ __forceinline__ void mm24(const float* __restrict__ AT,
                                     const float* __restrict__ B,
                                     int m0, int n0, ull acc[2][2]) {
#pragma unroll 8
    for (int k = 0; k < 64; ++k) {
        float2 av = *(const float2*)(AT + k * SA + m0);
        float4 bv = *(const float4*)(B  + k * SB + n0);
        ull b01 = pack2(bv.x, bv.y), b23 = pack2(bv.z, bv.w);
        ull a0 = pack2(av.x, av.x),  a1 = pack2(av.y, av.y);
        fma2(acc[0][0], a0, b01); fma2(acc[0][1], a0, b23);
        fma2(acc[1][0], a1, b01); fma2(acc[1][1], a1, b23);
    }
}

__device__ __forceinline__ void st_cluster_v4(uint32_t laddr, uint peer, float4 v) {
    uint32_t raddr;
    asm("mapa.shared::cluster.u32 %0, %1, %2;" : "=r"(raddr) : "r"(laddr), "r"(peer));
    asm volatile("st.shared::cluster.v4.b32 [%0], {%1,%2,%3,%4};"
                 :: "r"(raddr),
                    "r"(__float_as_uint(v.x)), "r"(__float_as_uint(v.y)),
                    "r"(__float_as_uint(v.z)), "r"(__float_as_uint(v.w))
                 : "memory");
}

__global__ void __launch_bounds__(768, 1) __cluster_dims__(2, 1, 1)
rec_kernel(const float* __restrict__ Wu1,
           const float* __restrict__ Wu2,
           float* __restrict__ out) {
    extern __shared__ float sm[];
    float* hbuf0 = sm;                       // [64][HX]
    float* hbuf1 = sm + 4096;                // [64][HX]
    float* w1T   = sm + 8192;                // [3][64][W1X]
    float* w2T   = sm + 8192 + 6144;         // [3][64][W2X]
    float* tmpT  = sm + 8192 + 6144 + 12288; // [3][64][TPX]
    float* buf   = tmpT + 3 * 64 * TPX;      // [2][32][BFX] (z, r)

    const int bid  = blockIdx.x;
    const int n    = bid >> 1;
    const int rank = bid & 1;
    const int tid  = threadIdx.x;
    const int g    = tid >> 8;               // gate group 0..2
    const int gt   = tid & 255;

    // stage1 thread mapping: M=64(j), N=32(a_l); warp spans 16 contiguous m, 2 n
    const int m10 = (((gt & 15) + ((gt >> 7) << 4)) << 1);  // 0..62
    const int n10 = (((gt >> 4) & 7) << 2);                 // 0..28
    // stage2 thread mapping: M=32(a_l), N=64(b); warp spans 16 contiguous m, 2 n
    const int m20 = ((gt & 15) << 1);                       // 0..30
    const int n20 = ((gt >> 4) << 2);                       // 0..60

    // weight load + transpose (one-time; conflicts here are negligible)
    for (int gg = 0; gg < 3; ++gg) {
        const float* w1 = Wu1 + gg * 4096;
        const float* w2 = Wu2 + gg * 4096;
        for (int e = tid; e < 2048; e += 768) {
            int a_l = e >> 6, i = e & 63;
            w1T[gg * 2048 + i * W1X + a_l] = w1[(32 * rank + a_l) * 64 + i];
        }
        for (int e = tid; e < 4096; e += 768) {
            int b = e >> 6, j = e & 63;
            w2T[gg * 4096 + j * W2X + b] = w2[b * 64 + j];
        }
    }
    for (int e = tid; e < 4096; e += 768) { hbuf0[e] = 0.f; hbuf1[e] = 0.f; }

    float cst[2][4] = {{0.f,0.f,0.f,0.f},{0.f,0.f,0.f,0.f}};

    uint32_t smem_u32;
    asm("{ .reg .u64 t; cvta.to.shared.u64 t, %1; cvt.u32.u64 %0, t; }"
        : "=r"(smem_u32) : "l"(sm));
    const uint peer = rank ^ 1;

    __syncthreads();
    asm volatile("barrier.cluster.arrive.aligned;" ::: "memory");
    asm volatile("barrier.cluster.wait.aligned;"   ::: "memory");

    const float* w1g = w1T + g * 2048;
    const float* w2g = w2T + g * 4096;
    float* tpg = tmpT + g * (64 * TPX);

    for (int l = 0; l < 128; ++l) {
        const float* hT = (l & 1) ? hbuf1 : hbuf0;
        float*       hN = (l & 1) ? hbuf0 : hbuf1;

        // prefetch this gate's xg tile (stage2 coords); hidden behind matmuls
        float gv[2][4];
        {
            const float* xb = g_xg + ((size_t)(l * 3 + g) * 64 + n) * 4096
                              + (32 * rank + m20) * 64 + n20;
            *(float4*)gv[0] = *(const float4*)xb;
            *(float4*)gv[1] = *(const float4*)(xb + 64);
        }

        // ---- stage1: tmpT[g][j][a_l] ----
        {
            ull acc[2][2] = {{pack2(0.f,0.f), pack2(0.f,0.f)},
                             {pack2(0.f,0.f), pack2(0.f,0.f)}};
            mm24<HX, W1X>(hT, w1g, m10, n10, acc);
#pragma unroll
            for (int rr = 0; rr < 2; ++rr) {
                float2 lo = unpack2(acc[rr][0]), hi = unpack2(acc[rr][1]);
                *(float4*)(tpg + (m10 + rr) * TPX + n10) =
                    make_float4(lo.x, lo.y, hi.x, hi.y);
            }
        }
        // per-group barrier (stage1 -> stage2 handoff stays inside the group)
        asm volatile("bar.sync %0, 256;" :: "r"(g + 1) : "memory");

        // ---- stage2: hg[a_l][b]; add xg; sigmoid ----
        {
            ull acc[2][2] = {{pack2(0.f,0.f), pack2(0.f,0.f)},
                             {pack2(0.f,0.f), pack2(0.f,0.f)}};
            mm24<TPX, W2X>(tpg, w2g, m20, n20, acc);
#pragma unroll
            for (int rr = 0; rr < 2; ++rr) {
                float2 lo = unpack2(acc[rr][0]), hi = unpack2(acc[rr][1]);
                gv[rr][0] = sigmoidf(gv[rr][0] + lo.x);
                gv[rr][1] = sigmoidf(gv[rr][1] + lo.y);
                gv[rr][2] = sigmoidf(gv[rr][2] + hi.x);
                gv[rr][3] = sigmoidf(gv[rr][3] + hi.y);
            }
        }
        if (g < 2) {   // z and r go to smem for group 2
#pragma unroll
            for (int rr = 0; rr < 2; ++rr)
                *(float4*)(buf + g * (32 * BFX) + (m20 + rr) * BFX + n20) =
                    make_float4(gv[rr][0], gv[rr][1], gv[rr][2], gv[rr][3]);
        }
        __syncthreads();   // buf ready

        if (g == 2) {      // owns o + c state: elementwise update, write h
#pragma unroll
            for (int rr = 0; rr < 2; ++rr) {
                int row_l = m20 + rr;
                float4 z4 = *(const float4*)(buf + row_l * BFX + n20);
                float4 r4 = *(const float4*)(buf + 32 * BFX + row_l * BFX + n20);
                float zz[4] = {z4.x, z4.y, z4.z, z4.w};
                float rrv[4] = {r4.x, r4.y, r4.z, r4.w};
                float hv[4];
#pragma unroll
                for (int q = 0; q < 4; ++q) {
                    float cn = rrv[q] * (cst[rr][q] + zz[q]);  // c = r*c + z*r
                    cst[rr][q] = cn;
                    hv[q] = gv[rr][q] * sigmoidf(cn);          // h = o*sig(c)
                }
                float4 h4 = make_float4(hv[0], hv[1], hv[2], hv[3]);
                int row_g = 32 * rank + row_l;
                *(float4*)(hN + row_g * HX + n20) = h4;        // local h
                uint32_t laddr = smem_u32 +
                    (uint32_t)(((hN - sm) + row_g * HX + n20) * 4);
                st_cluster_v4(laddr, peer, h4);                // peer h (DSMEM)
                *(float4*)(out + ((size_t)n * 128 + l) * 4096 + row_g * 64 + n20) = h4;
            }
        }
        // single cluster barrier: all h writes (local + DSMEM) visible next step
        asm volatile("barrier.cluster.arrive.aligned;" ::: "memory");
        asm volatile("barrier.cluster.wait.aligned;"   ::: "memory");
    }

    // epilogue: final h is in hbuf0 (written at l=127), synced cluster-wide.
    // outs = 33,554,432 floats; h_last at +33,554,432; c_last at +33,816,576.
    for (int e = tid; e < 2048; e += 768) {
        int a_l = e >> 6, b = e & 63;
        int row_g = 32 * rank + a_l;
        out[33554432ull + (size_t)n * 4096 + row_g * 64 + b] = hbuf0[row_g * HX + b];
    }
    if (g == 2) {
#pragma unroll
        for (int rr = 0; rr < 2; ++rr) {
            int row_g = 32 * rank + m20 + rr;
            float* cl = out + 33816576ull + (size_t)n * 4096 + row_g * 64 + n20;
            cl[0] = cst[rr][0]; cl[1] = cst[rr][1];
            cl[2] = cst[rr][2]; cl[3] = cst[rr][3];
        }
    }
}

// ============================================================================
extern "C" void kernel_launch(void* const* d_in, const int* in_sizes, int n_in,
                              void* d_out, int out_size) {
    const float* inputs = (const float*)d_in[0];   // (64,128,64,64)
    const float* Ww1    = (const float*)d_in[1];   // (4,64,64) — only g<3 used
    const float* Ww2    = (const float*)d_in[2];
    const float* Wu1    = (const float*)d_in[3];
    const float* Wu2    = (const float*)d_in[4];
    float* out = (float*)d_out;

    const int xg_smem  = 4 * 64 * SX * sizeof(float);
    const int rec_smem = (4096 * 2 + 3 * 64 * W1X + 3 * 64 * W2X +
                          3 * 64 * TPX + 2 * 32 * BFX) * sizeof(float);

    cudaFuncSetAttribute(xg_kernel,  cudaFuncAttributeMaxDynamicSharedMemorySize, xg_smem);
    cudaFuncSetAttribute(rec_kernel, cudaFuncAttributeMaxDynamicSharedMemorySize, rec_smem);

    xg_kernel<<<dim3(128, 64), 256, xg_smem>>>(inputs, Ww1, Ww2);
    rec_kernel<<<128, 768, rec_smem>>>(Wu1, Wu2, out);
}

// round 5
// speedup vs baseline: 1.0879x; 1.0879x over previous
#include <cuda_runtime.h>
#include <cstdint>

typedef unsigned long long ull;
typedef unsigned int uint;

__device__ __forceinline__ ull pack2(float lo, float hi) {
    ull r; asm("mov.b64 %0, {%1, %2};" : "=l"(r) : "f"(lo), "f"(hi)); return r;
}
__device__ __forceinline__ void fma2(ull& acc, ull a, ull b) {
    asm("fma.rn.f32x2 %0, %1, %2, %0;" : "+l"(acc) : "l"(a), "l"(b));
}
__device__ __forceinline__ float2 unpack2(ull v) {
    float2 r; asm("mov.b64 {%0, %1}, %2;" : "=f"(r.x), "=f"(r.y) : "l"(v)); return r;
}
__device__ __forceinline__ float sigmoidf(float x) {
    return __fdividef(1.0f, 1.0f + __expf(-x));
}

// 4x4 tile: C[m0..m0+3][n0..n0+3] += sum_k A[k][m] * B[k][n]
template <int SA, int SB>
__device__ __forceinline__ void mm44(const float* __restrict__ A,
                                     const float* __restrict__ B,
                                     int m0, int n0, ull acc[4][2]) {
#pragma unroll 8
    for (int k = 0; k < 64; ++k) {
        float4 av = *(const float4*)(A + k * SA + m0);
        float4 bv = *(const float4*)(B + k * SB + n0);
        ull b01 = pack2(bv.x, bv.y), b23 = pack2(bv.z, bv.w);
        ull a;
        a = pack2(av.x, av.x); fma2(acc[0][0], a, b01); fma2(acc[0][1], a, b23);
        a = pack2(av.y, av.y); fma2(acc[1][0], a, b01); fma2(acc[1][1], a, b23);
        a = pack2(av.z, av.z); fma2(acc[2][0], a, b01); fma2(acc[2][1], a, b23);
        a = pack2(av.w, av.w); fma2(acc[3][0], a, b01); fma2(acc[3][1], a, b23);
    }
}
__device__ __forceinline__ void zero4(ull acc[4][2]) {
#pragma unroll
    for (int r = 0; r < 4; ++r) { acc[r][0] = pack2(0.f,0.f); acc[r][1] = pack2(0.f,0.f); }
}

// 8x4 tile as two strips {m0..m0+3, m0+HALF..m0+HALF+3} (conflict-free A loads)
template <int SA, int SB, int HALF>
__device__ __forceinline__ void mm84(const float* __restrict__ A,
                                     const float* __restrict__ B,
                                     int m0, int n0, ull acc[8][2]) {
#pragma unroll 8
    for (int k = 0; k < 64; ++k) {
        float4 a0 = *(const float4*)(A + k * SA + m0);
        float4 a1 = *(const float4*)(A + k * SA + m0 + HALF);
        float4 bv = *(const float4*)(B + k * SB + n0);
        ull b01 = pack2(bv.x, bv.y), b23 = pack2(bv.z, bv.w);
        ull a;
        a = pack2(a0.x, a0.x); fma2(acc[0][0], a, b01); fma2(acc[0][1], a, b23);
        a = pack2(a0.y, a0.y); fma2(acc[1][0], a, b01); fma2(acc[1][1], a, b23);
        a = pack2(a0.z, a0.z); fma2(acc[2][0], a, b01); fma2(acc[2][1], a, b23);
        a = pack2(a0.w, a0.w); fma2(acc[3][0], a, b01); fma2(acc[3][1], a, b23);
        a = pack2(a1.x, a1.x); fma2(acc[4][0], a, b01); fma2(acc[4][1], a, b23);
        a = pack2(a1.y, a1.y); fma2(acc[5][0], a, b01); fma2(acc[5][1], a, b23);
        a = pack2(a1.z, a1.z); fma2(acc[6][0], a, b01); fma2(acc[6][1], a, b23);
        a = pack2(a1.w, a1.w); fma2(acc[7][0], a, b01); fma2(acc[7][1], a, b23);
    }
}
__device__ __forceinline__ void zero8(ull acc[8][2]) {
#pragma unroll
    for (int r = 0; r < 8; ++r) { acc[r][0] = pack2(0.f,0.f); acc[r][1] = pack2(0.f,0.f); }
}

__device__ __forceinline__ void st_cluster_v4(uint32_t laddr, uint peer, float4 v) {
    uint32_t raddr;
    asm("mapa.shared::cluster.u32 %0, %1, %2;" : "=r"(raddr) : "r"(laddr), "r"(peer));
    asm volatile("st.shared::cluster.v4.b32 [%0], {%1,%2,%3,%4};"
                 :: "r"(raddr),
                    "r"(__float_as_uint(v.x)), "r"(__float_as_uint(v.y)),
                    "r"(__float_as_uint(v.z)), "r"(__float_as_uint(v.w))
                 : "memory");
}

// xg scratch: [l][g][n][a][b]  (384 MB device .bss)
__device__ float g_xg[(size_t)3 * 128 * 64 * 64 * 64];

// ============================================================================
// Phase 1: xg[l,g,n,a,b] = Ww1[g] @ x[l,n] @ Ww2[g]^T.
// CTA = (l-pair, n); 256 threads = two 128-thread halves, one l each.
// Weights staged once per gate per CTA (amortized over 2 l's). 8x4 tiles.
// ============================================================================
#define XS 68

__global__ void __launch_bounds__(256, 2)
xg_kernel(const float* __restrict__ inputs,
          const float* __restrict__ Ww1,
          const float* __restrict__ Ww2) {
    extern __shared__ float sm[];
    float* xs  = sm;               // [2][64*XS]
    float* w1T = sm + 2 * 64 * XS; // [64*XS]  w1T[i][a]
    float* w2T = w1T + 64 * XS;    // [64*XS]  w2T[j][b]
    float* tmp = w2T + 64 * XS;    // [2][64*XS]  tmp[j][a]

    const int lp = blockIdx.x, n = blockIdx.y;
    const int tid = threadIdx.x;
    const int half = tid >> 7, ht = tid & 127;
    const int m0 = (ht & 7) * 4, n0 = (ht >> 3) * 4;
    const int l = lp * 2 + half;

    float* xsb  = xs  + half * (64 * XS);
    float* tmpb = tmp + half * (64 * XS);

    const float* xsrc = inputs + ((size_t)n * 128 + l) * 4096;
    for (int e = ht; e < 1024; e += 128) {
        int i = e >> 4, j4 = (e & 15) * 4;
        *(float4*)(xsb + i * XS + j4) = *(const float4*)(xsrc + i * 64 + j4);
    }

    for (int g = 0; g < 3; ++g) {
        __syncthreads();  // x visible (g=0); prior gate done with w1T/w2T
        for (int e = tid; e < 4096; e += 256) {
            int r = e >> 6, cc = e & 63;   // transpose on store
            w1T[cc * XS + r] = Ww1[g * 4096 + e];
            w2T[cc * XS + r] = Ww2[g * 4096 + e];
        }
        __syncthreads();

        ull acc[8][2];
        zero8(acc);
        mm84<XS, XS, 32>(xsb, w1T, m0, n0, acc);   // tmp[j][a]
#pragma unroll
        for (int r = 0; r < 4; ++r) {
            float2 lo = unpack2(acc[r][0]),   hi = unpack2(acc[r][1]);
            float2 lo2 = unpack2(acc[4+r][0]), hi2 = unpack2(acc[4+r][1]);
            *(float4*)(tmpb + (m0 + r) * XS + n0) = make_float4(lo.x, lo.y, hi.x, hi.y);
            *(float4*)(tmpb + (32 + m0 + r) * XS + n0) = make_float4(lo2.x, lo2.y, hi2.x, hi2.y);
        }
        asm volatile("bar.sync %0, 128;" :: "r"(half + 1) : "memory");

        zero8(acc);
        mm84<XS, XS, 32>(tmpb, w2T, m0, n0, acc);  // xg[a][b]
        float* dst = g_xg + ((size_t)(l * 3 + g) * 64 + n) * 4096;
#pragma unroll
        for (int r = 0; r < 4; ++r) {
            float2 lo = unpack2(acc[r][0]),   hi = unpack2(acc[r][1]);
            float2 lo2 = unpack2(acc[4+r][0]), hi2 = unpack2(acc[4+r][1]);
            *(float4*)(dst + (m0 + r) * 64 + n0) = make_float4(lo.x, lo.y, hi.x, hi.y);
            *(float4*)(dst + (32 + m0 + r) * 64 + n0) = make_float4(lo2.x, lo2.y, hi2.x, hi2.y);
        }
    }
}

// ============================================================================
// Phase 2: recurrence. Cluster-2 (rank owns 32 output rows), 384 threads =
// 3 gates x 4 warps, 4x4 tiles, c in gate-2 registers, ping-pong h + DSMEM,
// ONE cluster barrier per step.
// ============================================================================
#define HBX 68   // hbuf stride [i][j]
#define RW1 36   // w1T stride [i][a_l]
#define RW2 68   // w2T stride [j][b]
#define RTP 36   // tmpT stride [j][a_l]
#define RBF 68   // buf stride

__global__ void __launch_bounds__(384, 1) __cluster_dims__(2, 1, 1)
rec_kernel(const float* __restrict__ Wu1,
           const float* __restrict__ Wu2,
           float* __restrict__ out) {
    extern __shared__ float sm[];
    float* hbuf0 = sm;                 // [64][HBX] = 4352
    float* hbuf1 = sm + 4352;
    float* w1T   = sm + 8704;          // [3][64][RW1] = 6912
    float* w2T   = sm + 15616;         // [3][64][RW2] = 13056
    float* tmpT  = sm + 28672;         // [3][64][RTP] = 6912
    float* buf   = sm + 35584;         // [2][32][RBF] (z, r) = 4352

    const int bid  = blockIdx.x;
    const int n    = bid >> 1;
    const int rank = bid & 1;
    const int tid  = threadIdx.x;
    const int g    = tid >> 7;         // gate 0..2 (128 threads each)
    const int gt   = tid & 127;
    // stage1: M=64(j) x N=32(a_l): 16x8 tile grid
    const int m10 = (gt & 15) * 4, n10 = (gt >> 4) * 4;
    // stage2: M=32(a_l) x N=64(b): 8x16 tile grid
    const int m20 = (gt & 7) * 4,  n20 = (gt >> 3) * 4;

    for (int gg = 0; gg < 3; ++gg) {
        for (int e = tid; e < 2048; e += 384) {
            int al = e >> 6, i = e & 63;   // coalesced global read
            w1T[gg * (64*RW1) + i * RW1 + al] = Wu1[gg * 4096 + (32 * rank + al) * 64 + i];
        }
        for (int e = tid; e < 4096; e += 384) {
            int b = e >> 6, j = e & 63;
            w2T[gg * (64*RW2) + j * RW2 + b] = Wu2[gg * 4096 + b * 64 + j];
        }
    }
    for (int e = tid; e < 8704; e += 384) sm[e] = 0.f;   // hbuf0 + hbuf1

    float cst[4][4];
#pragma unroll
    for (int r = 0; r < 4; ++r)
#pragma unroll
        for (int q = 0; q < 4; ++q) cst[r][q] = 0.f;

    uint32_t smem_u32;
    asm("{ .reg .u64 t; cvta.to.shared.u64 t, %1; cvt.u32.u64 %0, t; }"
        : "=r"(smem_u32) : "l"(sm));
    const uint peer = rank ^ 1;

    __syncthreads();
    asm volatile("barrier.cluster.arrive.aligned;" ::: "memory");
    asm volatile("barrier.cluster.wait.aligned;"   ::: "memory");

    const float* w1g = w1T + g * (64 * RW1);
    const float* w2g = w2T + g * (64 * RW2);
    float* tpg = tmpT + g * (64 * RTP);

    for (int l = 0; l < 128; ++l) {
        const float* hT = (l & 1) ? hbuf1 : hbuf0;
        float*       hN = (l & 1) ? hbuf0 : hbuf1;

        // prefetch this gate's xg tile (stage2 coords); hidden behind stage1
        float gv[4][4];
        {
            const float* xb = g_xg + ((size_t)(l * 3 + g) * 64 + n) * 4096
                              + (32 * rank + m20) * 64 + n20;
#pragma unroll
            for (int r = 0; r < 4; ++r)
                *(float4*)gv[r] = *(const float4*)(xb + r * 64);
        }

        // ---- stage1: tmpT[j][a_l] = sum_i h[i][j] * w1T[i][a_l] ----
        {
            ull acc[4][2];
            zero4(acc);
            mm44<HBX, RW1>(hT, w1g, m10, n10, acc);
#pragma unroll
            for (int rr = 0; rr < 4; ++rr) {
                float2 lo = unpack2(acc[rr][0]), hi = unpack2(acc[rr][1]);
                *(float4*)(tpg + (m10 + rr) * RTP + n10) =
                    make_float4(lo.x, lo.y, hi.x, hi.y);
            }
        }
        asm volatile("bar.sync %0, 128;" :: "r"(g + 1) : "memory");

        // ---- stage2: hg[a_l][b] = sum_j tmpT[j][a_l] * w2T[j][b]; sigmoid ----
        {
            ull acc[4][2];
            zero4(acc);
            mm44<RTP, RW2>(tpg, w2g, m20, n20, acc);
#pragma unroll
            for (int rr = 0; rr < 4; ++rr) {
                float2 lo = unpack2(acc[rr][0]), hi = unpack2(acc[rr][1]);
                gv[rr][0] = sigmoidf(gv[rr][0] + lo.x);
                gv[rr][1] = sigmoidf(gv[rr][1] + lo.y);
                gv[rr][2] = sigmoidf(gv[rr][2] + hi.x);
                gv[rr][3] = sigmoidf(gv[rr][3] + hi.y);
            }
        }
        if (g < 2) {   // z, r -> smem for gate 2
#pragma unroll
            for (int rr = 0; rr < 4; ++rr)
                *(float4*)(buf + g * (32 * RBF) + (m20 + rr) * RBF + n20) =
                    make_float4(gv[rr][0], gv[rr][1], gv[rr][2], gv[rr][3]);
        }
        __syncthreads();   // buf ready

        if (g == 2) {      // owns o + c: elementwise, write h local/peer/out
#pragma unroll
            for (int rr = 0; rr < 4; ++rr) {
                int row_l = m20 + rr;
                float4 z4 = *(const float4*)(buf + row_l * RBF + n20);
                float4 r4 = *(const float4*)(buf + 32 * RBF + row_l * RBF + n20);
                float zz[4] = {z4.x, z4.y, z4.z, z4.w};
                float rv[4] = {r4.x, r4.y, r4.z, r4.w};
                float hv[4];
#pragma unroll
                for (int q = 0; q < 4; ++q) {
                    float cn = rv[q] * (cst[rr][q] + zz[q]);  // c = r*c + z*r
                    cst[rr][q] = cn;
                    hv[q] = gv[rr][q] * sigmoidf(cn);         // h = o*sig(c)
                }
                float4 h4 = make_float4(hv[0], hv[1], hv[2], hv[3]);
                int row_g = 32 * rank + row_l;
                *(float4*)(hN + row_g * HBX + n20) = h4;
                uint32_t laddr = smem_u32 +
                    (uint32_t)(((hN - sm) + row_g * HBX + n20) * 4);
                st_cluster_v4(laddr, peer, h4);
                *(float4*)(out + ((size_t)n * 128 + l) * 4096 + row_g * 64 + n20) = h4;
            }
        }
        asm volatile("barrier.cluster.arrive.aligned;" ::: "memory");
        asm volatile("barrier.cluster.wait.aligned;"   ::: "memory");
    }

    // epilogue: final h in hbuf0. outs = 33,554,432 floats.
    for (int e = tid; e < 2048; e += 384) {
        int al = e >> 6, b = e & 63;
        int row_g = 32 * rank + al;
        out[33554432ull + (size_t)n * 4096 + row_g * 64 + b] = hbuf0[row_g * HBX + b];
    }
    if (g == 2) {
#pragma unroll
        for (int rr = 0; rr < 4; ++rr) {
            int row_g = 32 * rank + m20 + rr;
            float* cl = out + 33816576ull + (size_t)n * 4096 + row_g * 64 + n20;
            cl[0] = cst[rr][0]; cl[1] = cst[rr][1];
            cl[2] = cst[rr][2]; cl[3] = cst[rr][3];
        }
    }
}

// ============================================================================
extern "C" void kernel_launch(void* const* d_in, const int* in_sizes, int n_in,
                              void* d_out, int out_size) {
    const float* inputs = (const float*)d_in[0];
    const float* Ww1    = (const float*)d_in[1];
    const float* Ww2    = (const float*)d_in[2];
    const float* Wu1    = (const float*)d_in[3];
    const float* Wu2    = (const float*)d_in[4];
    float* out = (float*)d_out;

    const int xg_smem  = 6 * 64 * XS * sizeof(float);          // 104448 B
    const int rec_smem = (35584 + 2 * 32 * RBF) * sizeof(float); // 159744 B

    cudaFuncSetAttribute(xg_kernel,  cudaFuncAttributeMaxDynamicSharedMemorySize, xg_smem);
    cudaFuncSetAttribute(rec_kernel, cudaFuncAttributeMaxDynamicSharedMemorySize, rec_smem);

    xg_kernel<<<dim3(64, 64), 256, xg_smem>>>(inputs, Ww1, Ww2);
    rec_kernel<<<128, 384, rec_smem>>>(Wu1, Wu2, out);
}